// round 5
// baseline (speedup 1.0000x reference)
#include <cuda_runtime.h>
#include <cstdint>
#include <math.h>

#define BETA   5.5f
#define NC     1000
#define NM     50
#define NR     51        // rows incl. vanilla
#define NP     26        // row-pairs (last pair holds only the vanilla row)
#define ND     1024
#define ND4    256
#define QB     125
#define QROWS  8
#define RSTAGE 3         // ring depth in pairs per warp
#define RING_F4 (4 * RSTAGE * 512)       // 4 warps * 3 slots * (2 rows * 256 f4)
#define SMEM_F4 (RING_F4 + 3 * 256)      // + qn/bk/bv
#define SMEM_BYTES (SMEM_F4 * 16)

__device__ __align__(16) float g_qn[ND];
__device__ float g_logits[NC];
__device__ float g_qpart[QB * ND];
__device__ unsigned int g_ctr_q = 0;
__device__ unsigned int g_ctr_m = 0;

__device__ __forceinline__ void cp16(uint32_t s, const void* g)
{
    asm volatile("cp.async.cg.shared.global [%0], [%1], 16;\n"
                 :: "r"(s), "l"(g) : "memory");
}
#define CP_COMMIT() asm volatile("cp.async.commit_group;\n" ::: "memory")
#define CP_WAIT(n)  asm volatile("cp.async.wait_group %0;\n" :: "n"(n) : "memory")

__device__ __forceinline__ float dot4(const float4 a, const float4 b)
{
    return a.x * b.x + a.y * b.y + a.z * b.z + a.w * b.w;
}

// ---------------------------------------------------------------------------
// Kernel 1: qn = l2norm(img + mean(global_bias,0)). grid=125 x 1024, ticketed.
// ---------------------------------------------------------------------------
__global__ void qn_kernel(const float* __restrict__ gb,
                          const float* __restrict__ img)
{
    const int d = threadIdx.x;
    const int b = blockIdx.x;
    const float* base = gb + (size_t)b * QROWS * ND + d;
    float s = 0.0f;
    #pragma unroll
    for (int r = 0; r < QROWS; ++r) s += base[r * ND];
    g_qpart[b * ND + d] = s;

    __shared__ unsigned int ticket;
    __threadfence();
    __syncthreads();
    if (d == 0) ticket = atomicAdd(&g_ctr_q, 1u);
    __syncthreads();
    if (ticket != QB - 1) return;

    float tsum = 0.0f;
    #pragma unroll 5
    for (int bb = 0; bb < QB; ++bb) tsum += g_qpart[bb * ND + d];
    const float q = img[d] + tsum * (1.0f / (float)NC);

    __shared__ float red[32];
    float v = q * q;
    #pragma unroll
    for (int o = 16; o; o >>= 1) v += __shfl_xor_sync(0xffffffffu, v, o);
    const int w = d >> 5, lane = d & 31;
    if (lane == 0) red[w] = v;
    __syncthreads();
    float tot = 0.0f;
    #pragma unroll
    for (int i = 0; i < 32; ++i) tot += red[i];

    g_qn[d] = q * rsqrtf(tot);
    if (d == 0) g_ctr_q = 0;
}

// ---------------------------------------------------------------------------
// issue cp.async for pair p into slot (2 rows x 1024 floats)
// ---------------------------------------------------------------------------
__device__ __forceinline__ void load_pair(uint32_t slot_s,
                                          const float4* __restrict__ mem4c,
                                          const float4* __restrict__ van4,
                                          int p, int lane)
{
    const int m0 = 2 * p;
    const int m1 = 2 * p + 1;
    const float4* r0 = (m0 < NM) ? (mem4c + (size_t)m0 * ND4) : van4;
    #pragma unroll
    for (int j = 0; j < 8; ++j)
        cp16(slot_s + (uint32_t)(j * 32 + lane) * 16u, r0 + j * 32 + lane);
    if (m1 < NR) {
        const float4* r1 = (m1 < NM) ? (mem4c + (size_t)m1 * ND4) : van4;
        const uint32_t s1 = slot_s + 256u * 16u;
        #pragma unroll
        for (int j = 0; j < 8; ++j)
            cp16(s1 + (uint32_t)(j * 32 + lane) * 16u, r1 + j * 32 + lane);
    }
}

// ---------------------------------------------------------------------------
// Kernel 2: per-class attention, warp-per-pair, cp.async ring, no mainloop
// barriers. grid=1000, block=128. Last block does the softmax.
// ---------------------------------------------------------------------------
__global__ void __launch_bounds__(128, 2)
dualmem_main_kernel(const float* __restrict__ mem,
                    const float* __restrict__ van,
                    const float* __restrict__ gbk,
                    const float* __restrict__ gbv,
                    const float* __restrict__ ffn,
                    const float* __restrict__ img,
                    const float* __restrict__ scale,
                    float* __restrict__ out)
{
    extern __shared__ float4 smem[];
    float4* ring = smem;                    // [4 warps][RSTAGE][512 f4]
    float4* qn_s = smem + RING_F4;
    float4* bk_s = qn_s + 256;
    float4* bv_s = bk_s + 256;

    __shared__ float  sw_s[4];
    __shared__ float4 redc[4];
    __shared__ float  red1[4];
    __shared__ float2 red2[4];
    __shared__ float  redm[4], reds[4];
    __shared__ unsigned int ticket;

    const int c    = blockIdx.x;
    const int t    = threadIdx.x;       // 0..127
    const int wi   = t >> 5;
    const int lane = t & 31;

    const float4* qn4  = (const float4*)g_qn;
    const float4* gbk4 = (const float4*)(gbk + (size_t)c * ND);
    const float4* gbv4 = (const float4*)(gbv + (size_t)c * ND);
    const float4* mem4 = (const float4*)(mem + (size_t)c * NM * ND);
    const float4* van4 = (const float4*)(van + (size_t)c * ND);

    // warp wi handles pairs p = wi, wi+4, ... ; pair count:
    const int np = (NP - wi + 3) >> 2;          // 7,7,6,6
    const uint32_t ring_s =
        (uint32_t)__cvta_generic_to_shared(ring + (size_t)wi * RSTAGE * 512);

    // --- kick off the ring first: get DRAM going ---
    #pragma unroll
    for (int i = 0; i < RSTAGE; ++i) {
        load_pair(ring_s + (uint32_t)i * 512u * 16u, mem4, van4, wi + 4 * i, lane);
        CP_COMMIT();
    }

    // --- stage qn/bk/bv + per-class constants ---
    float pqk = 0.0f, pkk = 0.0f, pvv = 0.0f;
    #pragma unroll
    for (int r = 0; r < 2; ++r) {
        const int idx = t + r * 128;
        const float4 q = qn4[idx];
        const float4 k = gbk4[idx];
        const float4 v = gbv4[idx];
        qn_s[idx] = q; bk_s[idx] = k; bv_s[idx] = v;
        pqk += dot4(q, k);
        pkk += dot4(k, k);
        pvv += dot4(v, v);
    }
    #pragma unroll
    for (int o = 16; o; o >>= 1) {
        pqk += __shfl_xor_sync(0xffffffffu, pqk, o);
        pkk += __shfl_xor_sync(0xffffffffu, pkk, o);
        pvv += __shfl_xor_sync(0xffffffffu, pvv, o);
    }
    if (lane == 0) redc[wi] = make_float4(pqk, pkk, pvv, 0.0f);
    __syncthreads();
    float qk_c = 0.0f, kk_c = 0.0f, vv_c = 0.0f;
    #pragma unroll
    for (int i = 0; i < 4; ++i) {
        qk_c += redc[i].x; kk_c += redc[i].y; vv_c += redc[i].z;
    }

    // --- mainloop (no block barriers) ---
    float4 acc[8];
    #pragma unroll
    for (int j = 0; j < 8; ++j) acc[j] = make_float4(0.f, 0.f, 0.f, 0.f);
    float sw = 0.0f;

    for (int i = 0; i < np; ++i) {
        const int p = wi + 4 * i;
        const int slot = i % RSTAGE;
        float4* sp = ring + ((size_t)wi * RSTAGE + slot) * 512;

        CP_WAIT(RSTAGE - 1);          // oldest pending group (this slot) is done
        __syncwarp();

        float4 x0[8], x1[8];
        float xx0 = 0.f, qx0 = 0.f, xk0 = 0.f, xv0 = 0.f;
        float xx1 = 0.f, qx1 = 0.f, xk1 = 0.f, xv1 = 0.f;
        #pragma unroll
        for (int j = 0; j < 8; ++j) {
            const int idx = j * 32 + lane;
            const float4 q = qn_s[idx];
            const float4 k = bk_s[idx];
            const float4 v = bv_s[idx];
            x0[j] = sp[idx];
            x1[j] = sp[256 + idx];
            xx0 += dot4(x0[j], x0[j]); qx0 += dot4(q, x0[j]);
            xk0 += dot4(k, x0[j]);     xv0 += dot4(v, x0[j]);
            xx1 += dot4(x1[j], x1[j]); qx1 += dot4(q, x1[j]);
            xk1 += dot4(k, x1[j]);     xv1 += dot4(v, x1[j]);
        }
        #pragma unroll
        for (int o = 16; o; o >>= 1) {
            xx0 += __shfl_xor_sync(0xffffffffu, xx0, o);
            qx0 += __shfl_xor_sync(0xffffffffu, qx0, o);
            xk0 += __shfl_xor_sync(0xffffffffu, xk0, o);
            xv0 += __shfl_xor_sync(0xffffffffu, xv0, o);
            xx1 += __shfl_xor_sync(0xffffffffu, xx1, o);
            qx1 += __shfl_xor_sync(0xffffffffu, qx1, o);
            xk1 += __shfl_xor_sync(0xffffffffu, xk1, o);
            xv1 += __shfl_xor_sync(0xffffffffu, xv1, o);
        }

        float w0 = 0.0f, w1 = 0.0f;
        if (xx0 != 0.0f) {
            const float dq = qx0 + qk_c;
            const float k2 = xx0 + 2.0f * xk0 + kk_c;
            const float v2 = xx0 + 2.0f * xv0 + vv_c;
            w0 = __expf(-BETA * (1.0f - dq * rsqrtf(k2))) * rsqrtf(v2);
        }
        if ((2 * p + 1) < NR && xx1 != 0.0f) {
            const float dq = qx1 + qk_c;
            const float k2 = xx1 + 2.0f * xk1 + kk_c;
            const float v2 = xx1 + 2.0f * xv1 + vv_c;
            w1 = __expf(-BETA * (1.0f - dq * rsqrtf(k2))) * rsqrtf(v2);
        }
        sw += w0 + w1;
        #pragma unroll
        for (int j = 0; j < 8; ++j) {
            acc[j].x += w0 * x0[j].x + w1 * x1[j].x;
            acc[j].y += w0 * x0[j].y + w1 * x1[j].y;
            acc[j].z += w0 * x0[j].z + w1 * x1[j].z;
            acc[j].w += w0 * x0[j].w + w1 * x1[j].w;
        }

        // refill this slot with pair i+RSTAGE (issued after all consuming FMAs)
        const int ip = i + RSTAGE;
        if (ip < np)
            load_pair(ring_s + (uint32_t)slot * 512u * 16u, mem4, van4,
                      wi + 4 * ip, lane);
        CP_COMMIT();
    }
    CP_WAIT(0);

    // --- combine warps (reuse ring as scratch) ---
    __syncthreads();                      // all warps done with their slots
    float4* accs = ring;                  // [4][256]
    #pragma unroll
    for (int j = 0; j < 8; ++j) accs[wi * 256 + j * 32 + lane] = acc[j];
    if (lane == 0) sw_s[wi] = sw;
    __syncthreads();

    const float swt = sw_s[0] + sw_s[1] + sw_s[2] + sw_s[3];
    float4 a0, a1;
    {
        const int i0 = t, i1 = t + 128;
        float4 s0 = accs[i0], s1 = accs[i1];
        #pragma unroll
        for (int w = 1; w < 4; ++w) {
            const float4 p = accs[w * 256 + i0], q = accs[w * 256 + i1];
            s0.x += p.x; s0.y += p.y; s0.z += p.z; s0.w += p.w;
            s1.x += q.x; s1.y += q.y; s1.z += q.z; s1.w += q.w;
        }
        const float4 b0 = bv_s[i0], b1 = bv_s[i1];
        a0 = make_float4(s0.x + swt*b0.x, s0.y + swt*b0.y, s0.z + swt*b0.z, s0.w + swt*b0.w);
        a1 = make_float4(s1.x + swt*b1.x, s1.y + swt*b1.y, s1.z + swt*b1.z, s1.w + swt*b1.w);
    }

    float n1 = dot4(a0, a0) + dot4(a1, a1);
    #pragma unroll
    for (int o = 16; o; o >>= 1) n1 += __shfl_xor_sync(0xffffffffu, n1, o);
    if (lane == 0) red1[wi] = n1;
    __syncthreads();
    const float rin1 = rsqrtf(red1[0] + red1[1] + red1[2] + red1[3]);

    const float4* ffn4 = (const float4*)(ffn + (size_t)c * ND);
    const float4* img4 = (const float4*)img;
    const float4 f0 = ffn4[t], f1 = ffn4[t + 128];
    const float4 i0 = img4[t], i1 = img4[t + 128];
    const float4 af0 = make_float4(a0.x*rin1 + f0.x, a0.y*rin1 + f0.y,
                                   a0.z*rin1 + f0.z, a0.w*rin1 + f0.w);
    const float4 af1 = make_float4(a1.x*rin1 + f1.x, a1.y*rin1 + f1.y,
                                   a1.z*rin1 + f1.z, a1.w*rin1 + f1.w);

    float n2 = dot4(af0, af0) + dot4(af1, af1);
    float dp = dot4(af0, i0) + dot4(af1, i1);
    #pragma unroll
    for (int o = 16; o; o >>= 1) {
        n2 += __shfl_xor_sync(0xffffffffu, n2, o);
        dp += __shfl_xor_sync(0xffffffffu, dp, o);
    }
    if (lane == 0) red2[wi] = make_float2(n2, dp);
    __syncthreads();

    if (t == 0) {
        float n2t = 0.0f, dpt = 0.0f;
        #pragma unroll
        for (int i = 0; i < 4; ++i) { n2t += red2[i].x; dpt += red2[i].y; }
        g_logits[c] = expf(scale[0]) * dpt * rsqrtf(n2t);
    }

    // --- last CTA: softmax over g_logits ---
    __threadfence();
    __syncthreads();
    if (t == 0) ticket = atomicAdd(&g_ctr_m, 1u);
    __syncthreads();
    if (ticket != NC - 1) return;

    float x[8];
    #pragma unroll
    for (int k = 0; k < 8; ++k) {
        const int i = t + k * 128;
        x[k] = (i < NC) ? g_logits[i] : -INFINITY;
    }
    float mx = x[0];
    #pragma unroll
    for (int k = 1; k < 8; ++k) mx = fmaxf(mx, x[k]);
    #pragma unroll
    for (int o = 16; o; o >>= 1) mx = fmaxf(mx, __shfl_xor_sync(0xffffffffu, mx, o));
    if (lane == 0) redm[wi] = mx;
    __syncthreads();
    mx = fmaxf(fmaxf(redm[0], redm[1]), fmaxf(redm[2], redm[3]));

    float e[8];
    float es = 0.0f;
    #pragma unroll
    for (int k = 0; k < 8; ++k) {
        const int i = t + k * 128;
        e[k] = (i < NC) ? expf(x[k] - mx) : 0.0f;
        es += e[k];
    }
    #pragma unroll
    for (int o = 16; o; o >>= 1) es += __shfl_xor_sync(0xffffffffu, es, o);
    if (lane == 0) reds[wi] = es;
    __syncthreads();
    const float rst = 1.0f / (reds[0] + reds[1] + reds[2] + reds[3]);

    #pragma unroll
    for (int k = 0; k < 8; ++k) {
        const int i = t + k * 128;
        if (i < NC) out[i] = e[k] * rst;
    }
    if (t == 0) g_ctr_m = 0;
}

// ---------------------------------------------------------------------------
extern "C" void kernel_launch(void* const* d_in, const int* in_sizes, int n_in,
                              void* d_out, int out_size)
{
    const float* img   = (const float*)d_in[0];
    const float* mem   = (const float*)d_in[1];
    const float* van   = (const float*)d_in[2];
    const float* gb    = (const float*)d_in[3];
    const float* gbk   = (const float*)d_in[4];
    const float* gbv   = (const float*)d_in[5];
    const float* ffn   = (const float*)d_in[6];
    const float* scale = (const float*)d_in[7];

    static bool configured = false;
    if (!configured) {
        cudaFuncSetAttribute(dualmem_main_kernel,
                             cudaFuncAttributeMaxDynamicSharedMemorySize,
                             SMEM_BYTES);
        configured = true;
    }

    qn_kernel<<<QB, 1024>>>(gb, img);
    dualmem_main_kernel<<<NC, 128, SMEM_BYTES>>>(mem, van, gbk, gbv, ffn, img,
                                                 scale, (float*)d_out);
}